// round 7
// baseline (speedup 1.0000x reference)
#include <cuda_runtime.h>
#include <cstdint>

#define NT      512
#define VPT     8                 // float4 per thread (8*512 = 4096 >= 4000)
#define HALF4   4000              // float4 per half-row
#define N_COLS  32000
#define N_ITER  50

__device__ __forceinline__ uint32_t smem_u32(const void* p) {
    uint32_t a;
    asm("{ .reg .u64 t; cvta.to.shared.u64 t, %1; cvt.u32.u64 %0, t; }"
        : "=r"(a) : "l"(p));
    return a;
}
__device__ __forceinline__ void st_cluster_f32(uint32_t laddr, uint32_t peer_rank, float v) {
    asm volatile(
        "{ .reg .b32 r; mapa.shared::cluster.u32 r, %0, %1; st.shared::cluster.f32 [r], %2; }"
        :: "r"(laddr), "r"(peer_rank), "f"(v) : "memory");
}
#define CLUSTER_SYNC() do { \
    asm volatile("barrier.cluster.arrive.aligned;" ::: "memory"); \
    asm volatile("barrier.cluster.wait.aligned;"   ::: "memory"); \
} while (0)

__device__ __forceinline__ float warp_sum(float v) {
    #pragma unroll
    for (int o = 16; o > 0; o >>= 1) v += __shfl_xor_sync(0xffffffffu, v, o);
    return v;
}
__device__ __forceinline__ float warp_max(float v) {
    #pragma unroll
    for (int o = 16; o > 0; o >>= 1) v = fmaxf(v, __shfl_xor_sync(0xffffffffu, v, o));
    return v;
}
__device__ __forceinline__ float warp_min(float v) {
    #pragma unroll
    for (int o = 16; o > 0; o >>= 1) v = fminf(v, __shfl_xor_sync(0xffffffffu, v, o));
    return v;
}

__global__ void __launch_bounds__(NT, 2) __cluster_dims__(2, 1, 1)
entmax_kernel(const float* __restrict__ x, float* __restrict__ out) {
    __shared__ float s_a[16];
    __shared__ float s_b[16];
    __shared__ float s_bc0;
    __shared__ float s_bc1;
    __shared__ float mbox[4];   // 0: peer max, 1: peer min, 2/3: peer sum (ping-pong)

    const int tid = threadIdx.x;
    const int wid = tid >> 5;        // 0..15
    const int lid = tid & 31;

    uint32_t rank;
    asm("mov.u32 %0, %%cluster_ctarank;" : "=r"(rank));
    const uint32_t peer = rank ^ 1u;
    const int row = blockIdx.x >> 1;

    const float4* __restrict__ xrow =
        reinterpret_cast<const float4*>(x + (size_t)row * N_COLS) + rank * HALF4;
    float4* __restrict__ orow =
        reinterpret_cast<float4*>(out + (size_t)row * N_COLS) + rank * HALF4;

    const uint32_t mbox_addr = smem_u32(mbox);

    const float NEG_BIG = -1e30f;
    float4 v[VPT];

    // ---- load half-row into registers, fused local min/max ----
    float lmax = __int_as_float(0xff800000);  // -inf
    float lmin = __int_as_float(0x7f800000);  // +inf
    #pragma unroll
    for (int i = 0; i < VPT; i++) {
        const int idx = i * NT + tid;
        if (idx < HALF4) {                    // only i == 7 partially predicated
            v[i] = xrow[idx];
            lmax = fmaxf(lmax, fmaxf(fmaxf(v[i].x, v[i].y), fmaxf(v[i].z, v[i].w)));
            lmin = fminf(lmin, fminf(fminf(v[i].x, v[i].y), fminf(v[i].z, v[i].w)));
        } else {
            v[i] = make_float4(NEG_BIG, NEG_BIG, NEG_BIG, NEG_BIG);
        }
    }

    // ---- local block reduce max/min, then cross-CTA combine via mailbox ----
    lmax = warp_max(lmax);
    lmin = warp_min(lmin);
    if (lid == 0) { s_a[wid] = lmax; s_b[wid] = lmin; }
    __syncthreads();
    if (wid == 0) {
        float m = (lid < 16) ? s_a[lid] : -3.4e38f;
        float n = (lid < 16) ? s_b[lid] :  3.4e38f;
        m = warp_max(m);
        n = warp_min(n);
        if (lid == 0) {
            s_bc0 = m; s_bc1 = n;
            st_cluster_f32(mbox_addr + 0, peer, m);   // my partials -> peer's mbox
            st_cluster_f32(mbox_addr + 4, peer, n);
        }
    }
    __syncthreads();
    CLUSTER_SYNC();
    // symmetric combine: both CTAs compute bit-identical results
    const float maxv = fmaxf(s_bc0, mbox[0]);
    const float minv = fminf(s_bc1, mbox[1]);

    // ---- shift in place: z = 0.5 * (x - max); sentinels stay hugely negative ----
    #pragma unroll
    for (int i = 0; i < VPT; i++) {
        v[i].x = 0.5f * (v[i].x - maxv);
        v[i].y = 0.5f * (v[i].y - maxv);
        v[i].z = 0.5f * (v[i].z - maxv);
        v[i].w = 0.5f * (v[i].w - maxv);
    }

    // ---- scalar fp32 replica of reference recurrence under constraint>0
    //      invariant (tmax <- tau each iter, tmin fixed). Analytically valid
    //      when tau_1^2 > 1: f(tau) >= clip(0-tau)^2 = tau^2 (max elem has
    //      z = 0), f decreasing, all iterates <= tau_1. ----
    const float m_shift = minv - maxv;
    const float tmin0 = m_shift - 1.0f;
    float tmaxr = 0.0f;
    #pragma unroll
    for (int it = 0; it < N_ITER; it++) tmaxr = 0.5f * (tmin0 + tmaxr);
    const float tau_fast = 0.5f * (tmin0 + tmaxr);
    const bool fast = (m_shift <= -1.02f);

    // ---- unconditional sum pass at tau_fast (sentinels clip to 0) ----
    float s = 0.0f;
    #pragma unroll
    for (int i = 0; i < VPT; i++) {
        float d;
        d = fmaxf(v[i].x - tau_fast, 0.0f); s = fmaf(d, d, s);
        d = fmaxf(v[i].y - tau_fast, 0.0f); s = fmaf(d, d, s);
        d = fmaxf(v[i].z - tau_fast, 0.0f); s = fmaf(d, d, s);
        d = fmaxf(v[i].w - tau_fast, 0.0f); s = fmaf(d, d, s);
    }
    s = warp_sum(s);
    if (lid == 0) s_a[wid] = s;
    __syncthreads();
    if (wid == 0) {
        float t = (lid < 16) ? s_a[lid] : 0.0f;
        t = warp_sum(t);
        if (lid == 0) {
            s_bc0 = t;
            st_cluster_f32(mbox_addr + 8, peer, t);   // sum slot 2
        }
    }
    __syncthreads();
    CLUSTER_SYNC();

    float tau = tau_fast;
    float total = s_bc0 + mbox[2];

    if (!fast) {
        // ---- fallback: exact reference-semantics bisection over registers,
        //      cluster-combined each iteration (ping-pong mailbox slots).
        //      Never taken for this data; guards pathological inputs. ----
        float tmin = tmin0, tmax = 0.0f;
        for (int it = 0; it < N_ITER; it++) {
            const float t = 0.5f * (tmin + tmax);
            float ss = 0.0f;
            #pragma unroll
            for (int i = 0; i < VPT; i++) {
                float d;
                d = fmaxf(v[i].x - t, 0.0f); ss = fmaf(d, d, ss);
                d = fmaxf(v[i].y - t, 0.0f); ss = fmaf(d, d, ss);
                d = fmaxf(v[i].z - t, 0.0f); ss = fmaf(d, d, ss);
                d = fmaxf(v[i].w - t, 0.0f); ss = fmaf(d, d, ss);
            }
            ss = warp_sum(ss);
            if (lid == 0) s_a[wid] = ss;
            __syncthreads();
            const int slot = 2 + (it & 1);
            if (wid == 0) {
                float u = (lid < 16) ? s_a[lid] : 0.0f;
                u = warp_sum(u);
                if (lid == 0) {
                    s_bc0 = u;
                    st_cluster_f32(mbox_addr + 4u * slot, peer, u);
                }
            }
            __syncthreads();
            CLUSTER_SYNC();
            const float constraint = (s_bc0 + mbox[slot]) - 1.0f;
            if (constraint < 0.0f) tmin = t;
            if (constraint > 0.0f) tmax = t;
        }
        tau = 0.5f * (tmin + tmax);
        float ss = 0.0f;
        #pragma unroll
        for (int i = 0; i < VPT; i++) {
            float d;
            d = fmaxf(v[i].x - tau, 0.0f); ss = fmaf(d, d, ss);
            d = fmaxf(v[i].y - tau, 0.0f); ss = fmaf(d, d, ss);
            d = fmaxf(v[i].z - tau, 0.0f); ss = fmaf(d, d, ss);
            d = fmaxf(v[i].w - tau, 0.0f); ss = fmaf(d, d, ss);
        }
        ss = warp_sum(ss);
        if (lid == 0) s_a[wid] = ss;
        __syncthreads();
        if (wid == 0) {
            float u = (lid < 16) ? s_a[lid] : 0.0f;
            u = warp_sum(u);
            if (lid == 0) {
                s_bc0 = u;
                st_cluster_f32(mbox_addr + 8, peer, u);  // slot 2: last used iters ago
            }
        }
        __syncthreads();
        CLUSTER_SYNC();
        total = s_bc0 + mbox[2];
    }

    const float inv = 1.0f / (total + 1e-12f);

    // ---- write y = clip(z - tau)^2 * inv ----
    #pragma unroll
    for (int i = 0; i < VPT; i++) {
        const int idx = i * NT + tid;
        if (idx < HALF4) {
            float4 o;
            float d;
            d = fmaxf(v[i].x - tau, 0.0f); o.x = d * d * inv;
            d = fmaxf(v[i].y - tau, 0.0f); o.y = d * d * inv;
            d = fmaxf(v[i].z - tau, 0.0f); o.z = d * d * inv;
            d = fmaxf(v[i].w - tau, 0.0f); o.w = d * d * inv;
            orow[idx] = o;
        }
    }

    // no CTA may exit while a peer remote-store could still target its smem:
    // last remote store was ordered before the last CLUSTER_SYNC on both sides,
    // so nothing is in flight here.
}

extern "C" void kernel_launch(void* const* d_in, const int* in_sizes, int n_in,
                              void* d_out, int out_size) {
    const float* x = (const float*)d_in[0];
    float* out = (float*)d_out;
    const int rows = in_sizes[0] / N_COLS;      // 4096
    entmax_kernel<<<rows * 2, NT>>>(x, out);    // cluster dims (2,1,1) are static
}

// round 8
// speedup vs baseline: 1.0777x; 1.0777x over previous
#include <cuda_runtime.h>

#define NT      512
#define RV4     7                 // float4 per thread in registers
#define SJ      9                 // smem float4 iterations per thread
#define N_COLS  32000
#define N4      8000              // float4 per row
#define R4MAX   (RV4 * NT)        // 3584 float4 held in registers
#define SMEM4   (N4 - R4MAX)      // 4416 float4 held in smem
#define SMEM_BYTES (SMEM4 * 16)   // 70656
#define N_ITER  50

__device__ __forceinline__ float warp_sum(float v) {
    #pragma unroll
    for (int o = 16; o > 0; o >>= 1) v += __shfl_xor_sync(0xffffffffu, v, o);
    return v;
}
__device__ __forceinline__ float warp_max(float v) {
    #pragma unroll
    for (int o = 16; o > 0; o >>= 1) v = fmaxf(v, __shfl_xor_sync(0xffffffffu, v, o));
    return v;
}
__device__ __forceinline__ float warp_min(float v) {
    #pragma unroll
    for (int o = 16; o > 0; o >>= 1) v = fminf(v, __shfl_xor_sync(0xffffffffu, v, o));
    return v;
}

__global__ void __launch_bounds__(NT, 2)
entmax_kernel(const float* __restrict__ x, float* __restrict__ out) {
    extern __shared__ float4 sdat[];          // SMEM4 float4, thread-private slots
    __shared__ float s_a[16];
    __shared__ float s_b[16];
    __shared__ float s_bc0;
    __shared__ float s_bc1;

    const int row = blockIdx.x;
    const int tid = threadIdx.x;
    const int wid = tid >> 5;                 // 0..15
    const int lid = tid & 31;

    const float4* __restrict__ xrow =
        reinterpret_cast<const float4*>(x + (size_t)row * N_COLS);
    float4* __restrict__ orow =
        reinterpret_cast<float4*>(out + (size_t)row * N_COLS);

    float4 v[RV4];                            // raw x, never shifted

    // ---- load: reg part + smem part, fused local min/max ----
    float lmax = __int_as_float(0xff800000);  // -inf
    float lmin = __int_as_float(0x7f800000);  // +inf
    #pragma unroll
    for (int i = 0; i < RV4; i++) {
        v[i] = xrow[i * NT + tid];
        lmax = fmaxf(lmax, fmaxf(fmaxf(v[i].x, v[i].y), fmaxf(v[i].z, v[i].w)));
        lmin = fminf(lmin, fminf(fminf(v[i].x, v[i].y), fminf(v[i].z, v[i].w)));
    }
    #pragma unroll
    for (int j = 0; j < SJ; j++) {
        const int idx = R4MAX + j * NT + tid;
        if (idx < N4) {
            float4 a = xrow[idx];
            sdat[idx - R4MAX] = a;
            lmax = fmaxf(lmax, fmaxf(fmaxf(a.x, a.y), fmaxf(a.z, a.w)));
            lmin = fminf(lmin, fminf(fminf(a.x, a.y), fminf(a.z, a.w)));
        }
    }

    // ---- block reduce max & min (16 warps) ----
    lmax = warp_max(lmax);
    lmin = warp_min(lmin);
    if (lid == 0) { s_a[wid] = lmax; s_b[wid] = lmin; }
    __syncthreads();
    if (wid == 0) {
        float m = (lid < 16) ? s_a[lid] : -3.4e38f;
        float n = (lid < 16) ? s_b[lid] :  3.4e38f;
        m = warp_max(m);
        n = warp_min(n);
        if (lid == 0) { s_bc0 = m; s_bc1 = n; }
    }
    __syncthreads();
    const float maxv = s_bc0;
    const float minv = s_bc1;

    // ---- scalar fp32 replica of reference recurrence under constraint>0
    //      invariant (tmax <- tau each iter, tmin fixed). Analytically valid
    //      when tau_1^2 > 1: f(tau) >= clip(0-tau)^2 = tau^2 (max elem has
    //      z = 0), f decreasing, all iterates <= tau_1. ----
    const float m_shift = minv - maxv;
    const float tmin0 = m_shift - 1.0f;
    float tmaxr = 0.0f;
    #pragma unroll
    for (int it = 0; it < N_ITER; it++) tmaxr = 0.5f * (tmin0 + tmaxr);
    const float tau_fast = 0.5f * (tmin0 + tmaxr);
    const bool fast = (m_shift <= -1.02f);

    // folded constant: clip(0.5*(a - maxv) - tau, 0) == clip(fma(0.5, a, -c), 0)
    const float c_fast = 0.5f * maxv + tau_fast;

    // ---- unconditional sum pass at tau_fast ----
    float s = 0.0f;
    #pragma unroll
    for (int i = 0; i < RV4; i++) {
        float d;
        d = fmaxf(fmaf(0.5f, v[i].x, -c_fast), 0.0f); s = fmaf(d, d, s);
        d = fmaxf(fmaf(0.5f, v[i].y, -c_fast), 0.0f); s = fmaf(d, d, s);
        d = fmaxf(fmaf(0.5f, v[i].z, -c_fast), 0.0f); s = fmaf(d, d, s);
        d = fmaxf(fmaf(0.5f, v[i].w, -c_fast), 0.0f); s = fmaf(d, d, s);
    }
    #pragma unroll
    for (int j = 0; j < SJ; j++) {
        const int idx = R4MAX + j * NT + tid;
        if (idx < N4) {
            float4 a = sdat[idx - R4MAX];
            float d;
            d = fmaxf(fmaf(0.5f, a.x, -c_fast), 0.0f); s = fmaf(d, d, s);
            d = fmaxf(fmaf(0.5f, a.y, -c_fast), 0.0f); s = fmaf(d, d, s);
            d = fmaxf(fmaf(0.5f, a.z, -c_fast), 0.0f); s = fmaf(d, d, s);
            d = fmaxf(fmaf(0.5f, a.w, -c_fast), 0.0f); s = fmaf(d, d, s);
        }
    }
    s = warp_sum(s);
    if (lid == 0) s_a[wid] = s;
    __syncthreads();
    if (wid == 0) {
        float t = (lid < 16) ? s_a[lid] : 0.0f;
        t = warp_sum(t);
        if (lid == 0) s_bc0 = t;
    }
    __syncthreads();

    float cfin = c_fast;
    float total = s_bc0;

    if (!fast) {
        // ---- fallback: reference-semantics bisection (regs + smem).
        //      Never taken for this data; guards pathological inputs. ----
        float tmin = tmin0, tmax = 0.0f;
        for (int it = 0; it < N_ITER; it++) {
            const float t = 0.5f * (tmin + tmax);
            const float ct = 0.5f * maxv + t;
            float ss = 0.0f;
            #pragma unroll
            for (int i = 0; i < RV4; i++) {
                float d;
                d = fmaxf(fmaf(0.5f, v[i].x, -ct), 0.0f); ss = fmaf(d, d, ss);
                d = fmaxf(fmaf(0.5f, v[i].y, -ct), 0.0f); ss = fmaf(d, d, ss);
                d = fmaxf(fmaf(0.5f, v[i].z, -ct), 0.0f); ss = fmaf(d, d, ss);
                d = fmaxf(fmaf(0.5f, v[i].w, -ct), 0.0f); ss = fmaf(d, d, ss);
            }
            #pragma unroll
            for (int j = 0; j < SJ; j++) {
                const int idx = R4MAX + j * NT + tid;
                if (idx < N4) {
                    float4 a = sdat[idx - R4MAX];
                    float d;
                    d = fmaxf(fmaf(0.5f, a.x, -ct), 0.0f); ss = fmaf(d, d, ss);
                    d = fmaxf(fmaf(0.5f, a.y, -ct), 0.0f); ss = fmaf(d, d, ss);
                    d = fmaxf(fmaf(0.5f, a.z, -ct), 0.0f); ss = fmaf(d, d, ss);
                    d = fmaxf(fmaf(0.5f, a.w, -ct), 0.0f); ss = fmaf(d, d, ss);
                }
            }
            ss = warp_sum(ss);
            if (lid == 0) s_a[wid] = ss;
            __syncthreads();
            if (wid == 0) {
                float u = (lid < 16) ? s_a[lid] : 0.0f;
                u = warp_sum(u);
                if (lid == 0) s_bc0 = u;
            }
            __syncthreads();
            const float constraint = s_bc0 - 1.0f;
            if (constraint < 0.0f) tmin = t;
            if (constraint > 0.0f) tmax = t;
        }
        const float tau = 0.5f * (tmin + tmax);
        cfin = 0.5f * maxv + tau;
        float ss = 0.0f;
        #pragma unroll
        for (int i = 0; i < RV4; i++) {
            float d;
            d = fmaxf(fmaf(0.5f, v[i].x, -cfin), 0.0f); ss = fmaf(d, d, ss);
            d = fmaxf(fmaf(0.5f, v[i].y, -cfin), 0.0f); ss = fmaf(d, d, ss);
            d = fmaxf(fmaf(0.5f, v[i].z, -cfin), 0.0f); ss = fmaf(d, d, ss);
            d = fmaxf(fmaf(0.5f, v[i].w, -cfin), 0.0f); ss = fmaf(d, d, ss);
        }
        #pragma unroll
        for (int j = 0; j < SJ; j++) {
            const int idx = R4MAX + j * NT + tid;
            if (idx < N4) {
                float4 a = sdat[idx - R4MAX];
                float d;
                d = fmaxf(fmaf(0.5f, a.x, -cfin), 0.0f); ss = fmaf(d, d, ss);
                d = fmaxf(fmaf(0.5f, a.y, -cfin), 0.0f); ss = fmaf(d, d, ss);
                d = fmaxf(fmaf(0.5f, a.z, -cfin), 0.0f); ss = fmaf(d, d, ss);
                d = fmaxf(fmaf(0.5f, a.w, -cfin), 0.0f); ss = fmaf(d, d, ss);
            }
        }
        ss = warp_sum(ss);
        if (lid == 0) s_a[wid] = ss;
        __syncthreads();
        if (wid == 0) {
            float u = (lid < 16) ? s_a[lid] : 0.0f;
            u = warp_sum(u);
            if (lid == 0) s_bc0 = u;
        }
        __syncthreads();
        total = s_bc0;
    }

    const float inv = 1.0f / (total + 1e-12f);

    // ---- write y = clip(fma(0.5, x, -c), 0)^2 * inv ----
    #pragma unroll
    for (int i = 0; i < RV4; i++) {
        float4 o;
        float d;
        d = fmaxf(fmaf(0.5f, v[i].x, -cfin), 0.0f); o.x = d * d * inv;
        d = fmaxf(fmaf(0.5f, v[i].y, -cfin), 0.0f); o.y = d * d * inv;
        d = fmaxf(fmaf(0.5f, v[i].z, -cfin), 0.0f); o.z = d * d * inv;
        d = fmaxf(fmaf(0.5f, v[i].w, -cfin), 0.0f); o.w = d * d * inv;
        orow[i * NT + tid] = o;
    }
    #pragma unroll
    for (int j = 0; j < SJ; j++) {
        const int idx = R4MAX + j * NT + tid;
        if (idx < N4) {
            float4 a = sdat[idx - R4MAX];
            float4 o;
            float d;
            d = fmaxf(fmaf(0.5f, a.x, -cfin), 0.0f); o.x = d * d * inv;
            d = fmaxf(fmaf(0.5f, a.y, -cfin), 0.0f); o.y = d * d * inv;
            d = fmaxf(fmaf(0.5f, a.z, -cfin), 0.0f); o.z = d * d * inv;
            d = fmaxf(fmaf(0.5f, a.w, -cfin), 0.0f); o.w = d * d * inv;
            orow[idx] = o;
        }
    }
}

extern "C" void kernel_launch(void* const* d_in, const int* in_sizes, int n_in,
                              void* d_out, int out_size) {
    const float* x = (const float*)d_in[0];
    float* out = (float*)d_out;
    const int rows = in_sizes[0] / N_COLS;   // 4096
    cudaFuncSetAttribute(entmax_kernel,
                         cudaFuncAttributeMaxDynamicSharedMemorySize, SMEM_BYTES);
    entmax_kernel<<<rows, NT, SMEM_BYTES>>>(x, out);
}

// round 9
// speedup vs baseline: 1.0916x; 1.0129x over previous
#include <cuda_runtime.h>

#define NT      512
#define RV4     7                 // float4 per thread in registers
#define SJ      9                 // smem float4 iterations per thread
#define N_COLS  32000
#define N4      8000              // float4 per row
#define R4MAX   (RV4 * NT)        // 3584 float4 held in registers
#define SMEM4   (N4 - R4MAX)      // 4416 float4 held in smem
#define SMEM_BYTES (SMEM4 * 16)   // 70656
#define N_ITER  50

__device__ __forceinline__ float warp_sum(float v) {
    #pragma unroll
    for (int o = 16; o > 0; o >>= 1) v += __shfl_xor_sync(0xffffffffu, v, o);
    return v;
}
__device__ __forceinline__ float warp_max(float v) {
    #pragma unroll
    for (int o = 16; o > 0; o >>= 1) v = fmaxf(v, __shfl_xor_sync(0xffffffffu, v, o));
    return v;
}
__device__ __forceinline__ float warp_min(float v) {
    #pragma unroll
    for (int o = 16; o > 0; o >>= 1) v = fminf(v, __shfl_xor_sync(0xffffffffu, v, o));
    return v;
}

__global__ void __launch_bounds__(NT, 2)
entmax_kernel(const float* __restrict__ x, float* __restrict__ out) {
    extern __shared__ float4 sdat[];          // SMEM4 float4, thread-private slots
    __shared__ float s_mx[16];
    __shared__ float s_mn[16];
    __shared__ float s_s1[16];
    __shared__ float s_s2[16];
    __shared__ float s_bc0, s_bc1, s_bc2, s_bc3;

    const int row = blockIdx.x;
    const int tid = threadIdx.x;
    const int wid = tid >> 5;                 // 0..15
    const int lid = tid & 31;

    const float4* __restrict__ xrow =
        reinterpret_cast<const float4*>(x + (size_t)row * N_COLS);
    float4* __restrict__ orow =
        reinterpret_cast<float4*>(out + (size_t)row * N_COLS);

    float4 v[RV4];                            // raw x, never shifted

    // ---- load pass: reg part + smem part; fused max/min/S1/S2 ----
    float lmax = __int_as_float(0xff800000);  // -inf
    float lmin = __int_as_float(0x7f800000);  // +inf
    float s1 = 0.0f;                          // sum x
    float s2 = 0.0f;                          // sum x^2
    #pragma unroll
    for (int i = 0; i < RV4; i++) {
        float4 a = xrow[i * NT + tid];
        v[i] = a;
        lmax = fmaxf(lmax, fmaxf(fmaxf(a.x, a.y), fmaxf(a.z, a.w)));
        lmin = fminf(lmin, fminf(fminf(a.x, a.y), fminf(a.z, a.w)));
        s1 += a.x + a.y + a.z + a.w;
        s2 = fmaf(a.x, a.x, s2); s2 = fmaf(a.y, a.y, s2);
        s2 = fmaf(a.z, a.z, s2); s2 = fmaf(a.w, a.w, s2);
    }
    #pragma unroll
    for (int j = 0; j < SJ; j++) {
        const int idx = R4MAX + j * NT + tid;
        if (idx < N4) {
            float4 a = xrow[idx];
            sdat[idx - R4MAX] = a;
            lmax = fmaxf(lmax, fmaxf(fmaxf(a.x, a.y), fmaxf(a.z, a.w)));
            lmin = fminf(lmin, fminf(fminf(a.x, a.y), fminf(a.z, a.w)));
            s1 += a.x + a.y + a.z + a.w;
            s2 = fmaf(a.x, a.x, s2); s2 = fmaf(a.y, a.y, s2);
            s2 = fmaf(a.z, a.z, s2); s2 = fmaf(a.w, a.w, s2);
        }
    }

    // ---- single fused block reduce: max, min, S1, S2 ----
    lmax = warp_max(lmax);
    lmin = warp_min(lmin);
    s1 = warp_sum(s1);
    s2 = warp_sum(s2);
    if (lid == 0) { s_mx[wid] = lmax; s_mn[wid] = lmin; s_s1[wid] = s1; s_s2[wid] = s2; }
    __syncthreads();
    if (wid == 0) {
        float m = (lid < 16) ? s_mx[lid] : -3.4e38f;
        float n = (lid < 16) ? s_mn[lid] :  3.4e38f;
        float a = (lid < 16) ? s_s1[lid] : 0.0f;
        float b = (lid < 16) ? s_s2[lid] : 0.0f;
        m = warp_max(m);
        n = warp_min(n);
        a = warp_sum(a);
        b = warp_sum(b);
        if (lid == 0) { s_bc0 = m; s_bc1 = n; s_bc2 = a; s_bc3 = b; }
    }
    __syncthreads();
    const float maxv = s_bc0;
    const float minv = s_bc1;
    const float S1   = s_bc2;
    const float S2   = s_bc3;

    // ---- scalar fp32 replica of reference recurrence under constraint>0
    //      invariant (tmax <- tau each iter, tmin fixed). Analytically valid
    //      when tau_1^2 > 1: f(tau) >= clip(0-tau)^2 = tau^2 (max elem has
    //      z = 0), f decreasing, all iterates <= tau_1. ----
    const float m_shift = minv - maxv;
    const float tmin0 = m_shift - 1.0f;
    float tmaxr = 0.0f;
    #pragma unroll
    for (int it = 0; it < N_ITER; it++) tmaxr = 0.5f * (tmin0 + tmaxr);
    const float tau_fast = 0.5f * (tmin0 + tmaxr);
    const bool fast = (m_shift <= -1.02f);

    // folded constant: z - tau = fma(0.5, x, -c), c = 0.5*maxv + tau
    const float c_fast = 0.5f * maxv + tau_fast;

    // ---- analytic normalizer (fast path): clip never active because
    //      z_i - tau_fast >= 0.5*m_shift - (m_shift - 1) = 1 - 0.5*m_shift >= 1
    //      (m_shift <= 0). So f(tau) = sum (0.5 x - c)^2
    //                               = 0.25*S2 - c*S1 + N*c^2. ----
    float cfin  = c_fast;
    float total = fmaf(0.25f, S2, fmaf(-c_fast, S1, (float)N_COLS * c_fast * c_fast));

    if (!fast) {
        // ---- fallback: reference-semantics bisection (regs + smem).
        //      Never taken for this data; guards pathological inputs. ----
        float tmin = tmin0, tmax = 0.0f;
        for (int it = 0; it < N_ITER; it++) {
            const float t = 0.5f * (tmin + tmax);
            const float ct = 0.5f * maxv + t;
            float ss = 0.0f;
            #pragma unroll
            for (int i = 0; i < RV4; i++) {
                float d;
                d = fmaxf(fmaf(0.5f, v[i].x, -ct), 0.0f); ss = fmaf(d, d, ss);
                d = fmaxf(fmaf(0.5f, v[i].y, -ct), 0.0f); ss = fmaf(d, d, ss);
                d = fmaxf(fmaf(0.5f, v[i].z, -ct), 0.0f); ss = fmaf(d, d, ss);
                d = fmaxf(fmaf(0.5f, v[i].w, -ct), 0.0f); ss = fmaf(d, d, ss);
            }
            #pragma unroll
            for (int j = 0; j < SJ; j++) {
                const int idx = R4MAX + j * NT + tid;
                if (idx < N4) {
                    float4 a = sdat[idx - R4MAX];
                    float d;
                    d = fmaxf(fmaf(0.5f, a.x, -ct), 0.0f); ss = fmaf(d, d, ss);
                    d = fmaxf(fmaf(0.5f, a.y, -ct), 0.0f); ss = fmaf(d, d, ss);
                    d = fmaxf(fmaf(0.5f, a.z, -ct), 0.0f); ss = fmaf(d, d, ss);
                    d = fmaxf(fmaf(0.5f, a.w, -ct), 0.0f); ss = fmaf(d, d, ss);
                }
            }
            ss = warp_sum(ss);
            if (lid == 0) s_s1[wid] = ss;
            __syncthreads();
            if (wid == 0) {
                float u = (lid < 16) ? s_s1[lid] : 0.0f;
                u = warp_sum(u);
                if (lid == 0) s_bc0 = u;
            }
            __syncthreads();
            const float constraint = s_bc0 - 1.0f;
            if (constraint < 0.0f) tmin = t;
            if (constraint > 0.0f) tmax = t;
        }
        const float tau = 0.5f * (tmin + tmax);
        cfin = 0.5f * maxv + tau;
        float ss = 0.0f;
        #pragma unroll
        for (int i = 0; i < RV4; i++) {
            float d;
            d = fmaxf(fmaf(0.5f, v[i].x, -cfin), 0.0f); ss = fmaf(d, d, ss);
            d = fmaxf(fmaf(0.5f, v[i].y, -cfin), 0.0f); ss = fmaf(d, d, ss);
            d = fmaxf(fmaf(0.5f, v[i].z, -cfin), 0.0f); ss = fmaf(d, d, ss);
            d = fmaxf(fmaf(0.5f, v[i].w, -cfin), 0.0f); ss = fmaf(d, d, ss);
        }
        #pragma unroll
        for (int j = 0; j < SJ; j++) {
            const int idx = R4MAX + j * NT + tid;
            if (idx < N4) {
                float4 a = sdat[idx - R4MAX];
                float d;
                d = fmaxf(fmaf(0.5f, a.x, -cfin), 0.0f); ss = fmaf(d, d, ss);
                d = fmaxf(fmaf(0.5f, a.y, -cfin), 0.0f); ss = fmaf(d, d, ss);
                d = fmaxf(fmaf(0.5f, a.z, -cfin), 0.0f); ss = fmaf(d, d, ss);
                d = fmaxf(fmaf(0.5f, a.w, -cfin), 0.0f); ss = fmaf(d, d, ss);
            }
        }
        ss = warp_sum(ss);
        if (lid == 0) s_s1[wid] = ss;
        __syncthreads();
        if (wid == 0) {
            float u = (lid < 16) ? s_s1[lid] : 0.0f;
            u = warp_sum(u);
            if (lid == 0) s_bc0 = u;
        }
        __syncthreads();
        total = s_bc0;
    }

    const float inv = 1.0f / (total + 1e-12f);

    // ---- write y = clip(fma(0.5, x, -c), 0)^2 * inv ----
    #pragma unroll
    for (int i = 0; i < RV4; i++) {
        float4 o;
        float d;
        d = fmaxf(fmaf(0.5f, v[i].x, -cfin), 0.0f); o.x = d * d * inv;
        d = fmaxf(fmaf(0.5f, v[i].y, -cfin), 0.0f); o.y = d * d * inv;
        d = fmaxf(fmaf(0.5f, v[i].z, -cfin), 0.0f); o.z = d * d * inv;
        d = fmaxf(fmaf(0.5f, v[i].w, -cfin), 0.0f); o.w = d * d * inv;
        orow[i * NT + tid] = o;
    }
    #pragma unroll
    for (int j = 0; j < SJ; j++) {
        const int idx = R4MAX + j * NT + tid;
        if (idx < N4) {
            float4 a = sdat[idx - R4MAX];
            float4 o;
            float d;
            d = fmaxf(fmaf(0.5f, a.x, -cfin), 0.0f); o.x = d * d * inv;
            d = fmaxf(fmaf(0.5f, a.y, -cfin), 0.0f); o.y = d * d * inv;
            d = fmaxf(fmaf(0.5f, a.z, -cfin), 0.0f); o.z = d * d * inv;
            d = fmaxf(fmaf(0.5f, a.w, -cfin), 0.0f); o.w = d * d * inv;
            orow[idx] = o;
        }
    }
}

extern "C" void kernel_launch(void* const* d_in, const int* in_sizes, int n_in,
                              void* d_out, int out_size) {
    const float* x = (const float*)d_in[0];
    float* out = (float*)d_out;
    const int rows = in_sizes[0] / N_COLS;   // 4096
    cudaFuncSetAttribute(entmax_kernel,
                         cudaFuncAttributeMaxDynamicSharedMemorySize, SMEM_BYTES);
    entmax_kernel<<<rows, NT, SMEM_BYTES>>>(x, out);
}